// round 3
// baseline (speedup 1.0000x reference)
#include <cuda_runtime.h>
#include <math.h>

// DistillingLayer: conv1d(k=3, stride=2, pad=1, shared taps) -> ELU -> maxpool(k=3, stride=2, pad=1)
// x: (B=16, L=4096, D=512) f32, out: (B=16, Lp=1024, D=512) f32
//
// R2 change: kill the 1.15-wave tail. LP 8->16 (halo 9.4%->4.7%), block 256->128
// threads => grid = 1024 blocks that fit in ONE wave (6-7 blocks/SM, reg cap
// permits >=10), so no 136-block straggler wave throttling chip BW.

#define LP 16         // pool outputs per thread
#define D4 128        // D/4 float4 groups
#define L_IN 4096
#define LP_OUT 1024

__device__ __forceinline__ float elu1(float v) {
    // fast ELU: exp via MUFU.EX2; select keeps exact identity for v>0.
    float e = __expf(v) - 1.0f;
    return v > 0.0f ? v : e;
}

__device__ __forceinline__ float4 conv_elu(float4 a, float4 b, float4 c,
                                           float w0, float w1, float w2, float bias) {
    float4 r;
    r.x = elu1(fmaf(w0, a.x, fmaf(w1, b.x, fmaf(w2, c.x, bias))));
    r.y = elu1(fmaf(w0, a.y, fmaf(w1, b.y, fmaf(w2, c.y, bias))));
    r.z = elu1(fmaf(w0, a.z, fmaf(w1, b.z, fmaf(w2, c.z, bias))));
    r.w = elu1(fmaf(w0, a.w, fmaf(w1, b.w, fmaf(w2, c.w, bias))));
    return r;
}

__device__ __forceinline__ float4 max4(float4 a, float4 b) {
    float4 r;
    r.x = fmaxf(a.x, b.x);
    r.y = fmaxf(a.y, b.y);
    r.z = fmaxf(a.z, b.z);
    r.w = fmaxf(a.w, b.w);
    return r;
}

__global__ void __launch_bounds__(128)
distill_fused_kernel(const float* __restrict__ x,
                     const float* __restrict__ w,
                     const float* __restrict__ bptr,
                     float* __restrict__ out) {
    const int d4 = threadIdx.x;          // 0..127 channel group
    const int strip = blockIdx.x;        // 0..63  strip of LP pool rows
    const int b = blockIdx.y;            // 0..15  batch
    const int lp0 = strip * LP;

    const float w0 = __ldg(w);
    const float w1 = __ldg(w + 1);
    const float w2 = __ldg(w + 2);
    const float bias = __ldg(bptr);

    // float4 base pointers for this (batch, channel-group)
    const float4* xb = reinterpret_cast<const float4*>(x) + (size_t)b * L_IN * D4 + d4;
    float4* ob = reinterpret_cast<float4*>(out) + (size_t)b * LP_OUT * D4 + d4;

    float4 xprev;   // x[4*lp - 1] carried across iterations
    float4 ycarry;  // y[2*lp - 1] carried across iterations

    if (lp0 == 0) {
        // x[-1] is zero padding; y[-1] is -inf (maxpool pad excluded)
        xprev = make_float4(0.f, 0.f, 0.f, 0.f);
        ycarry = make_float4(-INFINITY, -INFINITY, -INFINITY, -INFINITY);
    } else {
        // prologue: y[2*lp0 - 1] needs x[4*lp0-3 .. 4*lp0-1]  (all in-range, lp0>=16)
        const int p = 4 * lp0 - 3;
        float4 a = xb[(size_t)p * D4];
        float4 c = xb[(size_t)(p + 1) * D4];
        float4 e = xb[(size_t)(p + 2) * D4];
        ycarry = conv_elu(a, c, e, w0, w1, w2, bias);
        xprev = e;
    }

#pragma unroll
    for (int i = 0; i < LP; i++) {
        const int lp = lp0 + i;
        const float4* xp = xb + (size_t)(4 * lp) * D4;
        // 4 independent loads (MLP=4): x[4lp], x[4lp+1], x[4lp+2], x[4lp+3]
        float4 x0 = xp[0];
        float4 x1 = xp[D4];
        float4 x2 = xp[2 * D4];
        float4 x3 = xp[3 * D4];

        float4 ye = conv_elu(xprev, x0, x1, w0, w1, w2, bias);  // y[2lp]
        float4 yo = conv_elu(x1, x2, x3, w0, w1, w2, bias);     // y[2lp+1]

        ob[(size_t)lp * D4] = max4(max4(ycarry, ye), yo);

        ycarry = yo;
        xprev = x3;
    }
}

extern "C" void kernel_launch(void* const* d_in, const int* in_sizes, int n_in,
                              void* d_out, int out_size) {
    const float* x = (const float*)d_in[0];
    const float* w = (const float*)d_in[1];
    const float* b = (const float*)d_in[2];
    float* out = (float*)d_out;

    // 64 strips per batch (LP=16), 16 batches => 1024 blocks of 128 threads.
    // One wave on 148 SMs (6-7 blocks/SM), ~1% imbalance, no tail wave.
    dim3 block(D4, 1);
    dim3 grid(LP_OUT / LP, 16);
    distill_fused_kernel<<<grid, block>>>(x, w, b, out);
}

// round 4
// speedup vs baseline: 1.0441x; 1.0441x over previous
#include <cuda_runtime.h>
#include <math.h>

// DistillingLayer: conv1d(k=3, stride=2, pad=1, shared taps) -> ELU -> maxpool(k=3, stride=2, pad=1)
// x: (B=16, L=4096, D=512) f32, out: (B=16, Lp=1024, D=512) f32
//
// R3 change: explicit 2-stage software pipeline. Previous SASS consumed x0
// right after the 4 loads, so the x0 scoreboard wait gated issue of the next
// iteration's loads -> sustained MLP << 4 -> DRAM stuck at 62%. Now iteration
// i+1's loads are issued BEFORE iteration i's compute (double-buffered in
// registers), keeping 8 LDG.128 in flight per warp. Stores use __stcs
// (streaming) since output is never re-read.

#define LP 16         // pool outputs per thread
#define D4 128        // D/4 float4 groups
#define L_IN 4096
#define LP_OUT 1024

__device__ __forceinline__ float elu1(float v) {
    float e = __expf(v) - 1.0f;
    return v > 0.0f ? v : e;
}

__device__ __forceinline__ float4 conv_elu(float4 a, float4 b, float4 c,
                                           float w0, float w1, float w2, float bias) {
    float4 r;
    r.x = elu1(fmaf(w0, a.x, fmaf(w1, b.x, fmaf(w2, c.x, bias))));
    r.y = elu1(fmaf(w0, a.y, fmaf(w1, b.y, fmaf(w2, c.y, bias))));
    r.z = elu1(fmaf(w0, a.z, fmaf(w1, b.z, fmaf(w2, c.z, bias))));
    r.w = elu1(fmaf(w0, a.w, fmaf(w1, b.w, fmaf(w2, c.w, bias))));
    return r;
}

__device__ __forceinline__ float4 max4(float4 a, float4 b) {
    float4 r;
    r.x = fmaxf(a.x, b.x);
    r.y = fmaxf(a.y, b.y);
    r.z = fmaxf(a.z, b.z);
    r.w = fmaxf(a.w, b.w);
    return r;
}

__global__ void __launch_bounds__(128, 8)
distill_fused_kernel(const float* __restrict__ x,
                     const float* __restrict__ w,
                     const float* __restrict__ bptr,
                     float* __restrict__ out) {
    const int d4 = threadIdx.x;          // 0..127 channel group
    const int strip = blockIdx.x;        // 0..63  strip of LP pool rows
    const int b = blockIdx.y;            // 0..15  batch
    const int lp0 = strip * LP;

    const float w0 = __ldg(w);
    const float w1 = __ldg(w + 1);
    const float w2 = __ldg(w + 2);
    const float bias = __ldg(bptr);

    const float4* xb = reinterpret_cast<const float4*>(x) + (size_t)b * L_IN * D4 + d4;
    float4* ob = reinterpret_cast<float4*>(out) + (size_t)b * LP_OUT * D4 + d4;

    float4 xprev;   // x[4*lp - 1] carried across iterations
    float4 ycarry;  // y[2*lp - 1] carried across iterations

    // ---- issue iteration 0's loads FIRST (they never depend on the carry) ----
    const float4* xp0 = xb + (size_t)(4 * lp0) * D4;
    float4 n0 = xp0[0];
    float4 n1 = xp0[D4];
    float4 n2 = xp0[2 * D4];
    float4 n3 = xp0[3 * D4];

    if (lp0 == 0) {
        xprev = make_float4(0.f, 0.f, 0.f, 0.f);
        ycarry = make_float4(-INFINITY, -INFINITY, -INFINITY, -INFINITY);
    } else {
        // prologue: y[2*lp0 - 1] needs x[4*lp0-3 .. 4*lp0-1]
        const int p = 4 * lp0 - 3;
        float4 a = xb[(size_t)p * D4];
        float4 c = xb[(size_t)(p + 1) * D4];
        float4 e = xb[(size_t)(p + 2) * D4];
        ycarry = conv_elu(a, c, e, w0, w1, w2, bias);
        xprev = e;
    }

#pragma unroll
    for (int i = 0; i < LP; i++) {
        // current iteration's data (already in flight / arrived)
        float4 x0 = n0, x1 = n1, x2 = n2, x3 = n3;

        // prefetch NEXT iteration's 4 loads before any consumption of x0..x3
        if (i + 1 < LP) {
            const float4* xp = xb + (size_t)(4 * (lp0 + i + 1)) * D4;
            n0 = xp[0];
            n1 = xp[D4];
            n2 = xp[2 * D4];
            n3 = xp[3 * D4];
        }

        float4 ye = conv_elu(xprev, x0, x1, w0, w1, w2, bias);  // y[2lp]
        float4 yo = conv_elu(x1, x2, x3, w0, w1, w2, bias);     // y[2lp+1]

        float4 o = max4(max4(ycarry, ye), yo);
        __stcs(&ob[(size_t)(lp0 + i) * D4], o);   // streaming store, skip L2 persist

        ycarry = yo;
        xprev = x3;
    }
}

extern "C" void kernel_launch(void* const* d_in, const int* in_sizes, int n_in,
                              void* d_out, int out_size) {
    const float* x = (const float*)d_in[0];
    const float* w = (const float*)d_in[1];
    const float* b = (const float*)d_in[2];
    float* out = (float*)d_out;

    dim3 block(D4, 1);
    dim3 grid(LP_OUT / LP, 16);   // 64 x 16 = 1024 blocks, one wave
    distill_fused_kernel<<<grid, block>>>(x, w, b, out);
}

// round 5
// speedup vs baseline: 1.0625x; 1.0176x over previous
#include <cuda_runtime.h>
#include <cuda_pipeline_primitives.h>
#include <math.h>

// DistillingLayer: conv1d(k=3, stride=2, pad=1, shared taps) -> ELU -> maxpool(k=3, stride=2, pad=1)
// x: (B=16, L=4096, D=512) f32, out: (B=16, Lp=1024, D=512) f32
//
// R4: cp.async SMEM pipeline. Register-scoreboard coupling capped sustained
// MLP in R1-R3 (DRAM stuck 60-65%). Now each thread streams its own 16B
// column through a 3-slot SMEM ring via cp.async (commit-group tracked, no
// reg scoreboard, no __syncthreads needed since columns are thread-private).
// Stage = 4 x-rows -> 1 pool row. 24KB SMEM/block, 128-thr blocks, 1024
// blocks = one wave.

#define LPB   16       // pool rows per block (stages per block)
#define D4    128      // D/4 float4 channel groups
#define RING  3        // smem ring depth
#define L_IN  4096
#define LP_OUT 1024

__device__ __forceinline__ float elu1(float v) {
    float e = __expf(v) - 1.0f;
    return v > 0.0f ? v : e;
}

__device__ __forceinline__ float4 conv_elu(float4 a, float4 b, float4 c,
                                           float w0, float w1, float w2, float bias) {
    float4 r;
    r.x = elu1(fmaf(w0, a.x, fmaf(w1, b.x, fmaf(w2, c.x, bias))));
    r.y = elu1(fmaf(w0, a.y, fmaf(w1, b.y, fmaf(w2, c.y, bias))));
    r.z = elu1(fmaf(w0, a.z, fmaf(w1, b.z, fmaf(w2, c.z, bias))));
    r.w = elu1(fmaf(w0, a.w, fmaf(w1, b.w, fmaf(w2, c.w, bias))));
    return r;
}

__device__ __forceinline__ float4 max4(float4 a, float4 b) {
    float4 r;
    r.x = fmaxf(a.x, b.x);
    r.y = fmaxf(a.y, b.y);
    r.z = fmaxf(a.z, b.z);
    r.w = fmaxf(a.w, b.w);
    return r;
}

__global__ void __launch_bounds__(128)
distill_fused_kernel(const float* __restrict__ x,
                     const float* __restrict__ w,
                     const float* __restrict__ bptr,
                     float* __restrict__ out) {
    const int d4 = threadIdx.x;          // 0..127 channel group (thread-private column)
    const int strip = blockIdx.x;        // 0..63
    const int b = blockIdx.y;            // 0..15
    const int lp0 = strip * LPB;

    const float w0 = __ldg(w);
    const float w1 = __ldg(w + 1);
    const float w2 = __ldg(w + 2);
    const float bias = __ldg(bptr);

    const float4* xb = reinterpret_cast<const float4*>(x) + (size_t)b * L_IN * D4 + d4;
    float4* ob = reinterpret_cast<float4*>(out) + (size_t)b * LP_OUT * D4 + d4;

    // SMEM ring: RING slots x 4 rows x 128 float4 columns = 24 KB
    __shared__ float4 sm[RING * 4 * D4];
    float4* mycol = sm + d4;   // this thread's column; row stride = D4

    // ---- prologue: issue first RING-1 stages (stage s = x rows 4*(lp0+s)..+3)
#pragma unroll
    for (int s = 0; s < RING - 1; s++) {
        const float4* src = xb + (size_t)(4 * (lp0 + s)) * D4;
        float4* dst = mycol + (size_t)(s * 4) * D4;
#pragma unroll
        for (int r = 0; r < 4; r++)
            __pipeline_memcpy_async(dst + (size_t)r * D4, src + (size_t)r * D4, 16);
        __pipeline_commit();
    }

    // ---- strip halo: ycarry = y[2*lp0 - 1], xprev = x[4*lp0 - 1]
    float4 xprev, ycarry;
    if (lp0 == 0) {
        xprev = make_float4(0.f, 0.f, 0.f, 0.f);
        ycarry = make_float4(-INFINITY, -INFINITY, -INFINITY, -INFINITY);
    } else {
        const int p = 4 * lp0 - 3;
        float4 a = xb[(size_t)p * D4];
        float4 c = xb[(size_t)(p + 1) * D4];
        float4 e = xb[(size_t)(p + 2) * D4];
        ycarry = conv_elu(a, c, e, w0, w1, w2, bias);
        xprev = e;
    }

    // ---- main loop: one pool row per stage
#pragma unroll 4
    for (int s = 0; s < LPB; s++) {
        // issue stage s + RING-1 (empty commit keeps group counting uniform)
        const int s2 = s + RING - 1;
        if (s2 < LPB) {
            const int slot2 = s2 % RING;
            const float4* src = xb + (size_t)(4 * (lp0 + s2)) * D4;
            float4* dst = mycol + (size_t)(slot2 * 4) * D4;
#pragma unroll
            for (int r = 0; r < 4; r++)
                __pipeline_memcpy_async(dst + (size_t)r * D4, src + (size_t)r * D4, 16);
        }
        __pipeline_commit();
        __pipeline_wait_prior(RING - 1);   // stage s's copies are complete

        const int slot = s % RING;
        const float4* st = mycol + (size_t)(slot * 4) * D4;
        float4 x0 = st[0];
        float4 x1 = st[(size_t)D4];
        float4 x2 = st[(size_t)2 * D4];
        float4 x3 = st[(size_t)3 * D4];

        float4 ye = conv_elu(xprev, x0, x1, w0, w1, w2, bias);  // y[2lp]
        float4 yo = conv_elu(x1, x2, x3, w0, w1, w2, bias);     // y[2lp+1]

        float4 o = max4(max4(ycarry, ye), yo);
        __stcs(&ob[(size_t)(lp0 + s) * D4], o);

        ycarry = yo;
        xprev = x3;
    }
}

extern "C" void kernel_launch(void* const* d_in, const int* in_sizes, int n_in,
                              void* d_out, int out_size) {
    const float* x = (const float*)d_in[0];
    const float* w = (const float*)d_in[1];
    const float* b = (const float*)d_in[2];
    float* out = (float*)d_out;

    dim3 block(D4, 1);
    dim3 grid(LP_OUT / LPB, 16);   // 64 x 16 = 1024 blocks, one wave
    distill_fused_kernel<<<grid, block>>>(x, w, b, out);
}

// round 6
// speedup vs baseline: 1.1275x; 1.0611x over previous
#include <cuda_runtime.h>
#include <cuda_pipeline_primitives.h>
#include <math.h>

// DistillingLayer: conv1d(k=3, stride=2, pad=1, shared taps) -> ELU -> maxpool(k=3, stride=2, pad=1)
// x: (B=16, L=4096, D=512) f32, out: (B=16, Lp=1024, D=512) f32
//
// R5: raise chip-level request parallelism. LP 16->8 doubles the grid to
// 2048 blocks / 8192 warps (36 resident warps/SM vs 27.7), keeping the
// per-thread cp.async ring (thread-private 16B columns, no __syncthreads).
// Halo re-reads (9.4% of x) largely hit L2 since neighbor strips run
// concurrently.

#define LPB   8        // pool rows per block (stages per block)
#define D4    128      // D/4 float4 channel groups
#define RING  3        // smem ring depth
#define L_IN  4096
#define LP_OUT 1024

__device__ __forceinline__ float elu1(float v) {
    float e = __expf(v) - 1.0f;
    return v > 0.0f ? v : e;
}

__device__ __forceinline__ float4 conv_elu(float4 a, float4 b, float4 c,
                                           float w0, float w1, float w2, float bias) {
    float4 r;
    r.x = elu1(fmaf(w0, a.x, fmaf(w1, b.x, fmaf(w2, c.x, bias))));
    r.y = elu1(fmaf(w0, a.y, fmaf(w1, b.y, fmaf(w2, c.y, bias))));
    r.z = elu1(fmaf(w0, a.z, fmaf(w1, b.z, fmaf(w2, c.z, bias))));
    r.w = elu1(fmaf(w0, a.w, fmaf(w1, b.w, fmaf(w2, c.w, bias))));
    return r;
}

__device__ __forceinline__ float4 max4(float4 a, float4 b) {
    float4 r;
    r.x = fmaxf(a.x, b.x);
    r.y = fmaxf(a.y, b.y);
    r.z = fmaxf(a.z, b.z);
    r.w = fmaxf(a.w, b.w);
    return r;
}

__global__ void __launch_bounds__(128)
distill_fused_kernel(const float* __restrict__ x,
                     const float* __restrict__ w,
                     const float* __restrict__ bptr,
                     float* __restrict__ out) {
    const int d4 = threadIdx.x;          // 0..127 channel group (thread-private column)
    const int strip = blockIdx.x;        // 0..127
    const int b = blockIdx.y;            // 0..15
    const int lp0 = strip * LPB;

    const float w0 = __ldg(w);
    const float w1 = __ldg(w + 1);
    const float w2 = __ldg(w + 2);
    const float bias = __ldg(bptr);

    const float4* xb = reinterpret_cast<const float4*>(x) + (size_t)b * L_IN * D4 + d4;
    float4* ob = reinterpret_cast<float4*>(out) + (size_t)b * LP_OUT * D4 + d4;

    // SMEM ring: RING slots x 4 rows x 128 float4 columns = 24 KB
    __shared__ float4 sm[RING * 4 * D4];
    float4* mycol = sm + d4;   // this thread's column; row stride = D4

    // ---- prologue: issue first RING-1 stages (stage s = x rows 4*(lp0+s)..+3)
#pragma unroll
    for (int s = 0; s < RING - 1; s++) {
        const float4* src = xb + (size_t)(4 * (lp0 + s)) * D4;
        float4* dst = mycol + (size_t)(s * 4) * D4;
#pragma unroll
        for (int r = 0; r < 4; r++)
            __pipeline_memcpy_async(dst + (size_t)r * D4, src + (size_t)r * D4, 16);
        __pipeline_commit();
    }

    // ---- strip halo: ycarry = y[2*lp0 - 1], xprev = x[4*lp0 - 1]
    float4 xprev, ycarry;
    if (lp0 == 0) {
        xprev = make_float4(0.f, 0.f, 0.f, 0.f);
        ycarry = make_float4(-INFINITY, -INFINITY, -INFINITY, -INFINITY);
    } else {
        const int p = 4 * lp0 - 3;
        float4 a = xb[(size_t)p * D4];
        float4 c = xb[(size_t)(p + 1) * D4];
        float4 e = xb[(size_t)(p + 2) * D4];
        ycarry = conv_elu(a, c, e, w0, w1, w2, bias);
        xprev = e;
    }

    // ---- main loop: one pool row per stage
#pragma unroll
    for (int s = 0; s < LPB; s++) {
        // issue stage s + RING-1 (empty commit keeps group counting uniform)
        const int s2 = s + RING - 1;
        if (s2 < LPB) {
            const int slot2 = s2 % RING;
            const float4* src = xb + (size_t)(4 * (lp0 + s2)) * D4;
            float4* dst = mycol + (size_t)(slot2 * 4) * D4;
#pragma unroll
            for (int r = 0; r < 4; r++)
                __pipeline_memcpy_async(dst + (size_t)r * D4, src + (size_t)r * D4, 16);
        }
        __pipeline_commit();
        __pipeline_wait_prior(RING - 1);   // stage s's copies are complete

        const int slot = s % RING;
        const float4* st = mycol + (size_t)(slot * 4) * D4;
        float4 x0 = st[0];
        float4 x1 = st[(size_t)D4];
        float4 x2 = st[(size_t)2 * D4];
        float4 x3 = st[(size_t)3 * D4];

        float4 ye = conv_elu(xprev, x0, x1, w0, w1, w2, bias);  // y[2lp]
        float4 yo = conv_elu(x1, x2, x3, w0, w1, w2, bias);     // y[2lp+1]

        float4 o = max4(max4(ycarry, ye), yo);
        __stcs(&ob[(size_t)(lp0 + s) * D4], o);

        ycarry = yo;
        xprev = x3;
    }
}

extern "C" void kernel_launch(void* const* d_in, const int* in_sizes, int n_in,
                              void* d_out, int out_size) {
    const float* x = (const float*)d_in[0];
    const float* w = (const float*)d_in[1];
    const float* b = (const float*)d_in[2];
    float* out = (float*)d_out;

    dim3 block(D4, 1);
    dim3 grid(LP_OUT / LPB, 16);   // 128 x 16 = 2048 blocks
    distill_fused_kernel<<<grid, block>>>(x, w, b, out);
}